// round 1
// baseline (speedup 1.0000x reference)
#include <cuda_runtime.h>
#include <math.h>

// ---------------------------------------------------------------------------
// Problem constants (fixed shapes)
// ---------------------------------------------------------------------------
#define BB     4
#define LL     2048
#define PP     1024
#define NFEAT  100
#define DD     1024
#define HH     8
#define HDIM   128
#define NHID   4096
#define NLAYERS 3
#define NOUTD  10
#define LB     (LL*BB)     // 8192 token rows
#define KPAD   112         // NFEAT padded to multiple of 16 (zero padded)

// ---------------------------------------------------------------------------
// Scratch (device globals; no allocation allowed)
// ---------------------------------------------------------------------------
__device__ float g_m1[BB*NFEAT], g_s1[BB*NFEAT];
__device__ float g_m2[BB*NFEAT], g_s2[BB*NFEAT];
__device__ float g_m3[BB*NFEAT], g_s3[BB*NFEAT];
__device__ float g_xn[(size_t)LB*KPAD];                 // normalized, padded input
__device__ float g_src[(size_t)LB*DD];                  // residual stream (B,L,D)
__device__ float g_h[(size_t)LB*DD];                    // LN output
__device__ float g_tmp[(size_t)LB*DD];                  // enc out / q raw / attn out
__device__ float g_kv[(size_t)BB*PP*2*DD];              // kv projections
__device__ float g_qh[(size_t)BB*HH*LL*HDIM];           // q per-head LN, (B,H,L,HD)
__device__ float g_kh[(size_t)BB*HH*PP*HDIM];           // k per-head LN, (B,H,P,HD)
__device__ float g_vh[(size_t)BB*HH*PP*HDIM];           // v, (B,H,P,HD)
__device__ float g_logits[(size_t)BB*HH*LL*PP];         // attention logits/probs
__device__ float g_ff[(size_t)LB*NHID];                 // FFN hidden / head hidden

// ---------------------------------------------------------------------------
// Reductions
// ---------------------------------------------------------------------------
__device__ __forceinline__ float warpSum(float v) {
#pragma unroll
  for (int o = 16; o > 0; o >>= 1) v += __shfl_xor_sync(0xffffffffu, v, o);
  return v;
}

__device__ __forceinline__ float blockReduceSum(float v) {
  __shared__ float sh[32];
  int lane = threadIdx.x & 31, wid = threadIdx.x >> 5;
  v = warpSum(v);
  if (lane == 0) sh[wid] = v;
  __syncthreads();
  int nw = (blockDim.x + 31) >> 5;
  v = (threadIdx.x < nw) ? sh[threadIdx.x] : 0.f;
  if (wid == 0) {
    v = warpSum(v);
    if (lane == 0) sh[0] = v;
  }
  __syncthreads();
  float r = sh[0];
  __syncthreads();
  return r;
}

__device__ __forceinline__ float blockReduceMax(float v) {
  __shared__ float sh[32];
  int lane = threadIdx.x & 31, wid = threadIdx.x >> 5;
#pragma unroll
  for (int o = 16; o > 0; o >>= 1) v = fmaxf(v, __shfl_xor_sync(0xffffffffu, v, o));
  if (lane == 0) sh[wid] = v;
  __syncthreads();
  int nw = (blockDim.x + 31) >> 5;
  v = (threadIdx.x < nw) ? sh[threadIdx.x] : -3.4e38f;
  if (wid == 0) {
#pragma unroll
    for (int o = 16; o > 0; o >>= 1) v = fmaxf(v, __shfl_xor_sync(0xffffffffu, v, o));
    if (lane == 0) sh[0] = v;
  }
  __syncthreads();
  float r = sh[0];
  __syncthreads();
  return r;
}

__device__ __forceinline__ float gelu_f(float x) {
  return 0.5f * x * (1.0f + erff(x * 0.7071067811865475f));
}

// ---------------------------------------------------------------------------
// Preprocessing: per-(b,f) stats over first PP rows (3 passes mirroring ref)
// mode 0: raw; mode 1: clip1(raw); mode 2: normalized(clip1(raw))
// ---------------------------------------------------------------------------
__global__ void __launch_bounds__(256) colstats_kernel(const float* __restrict__ xsrc, int mode) {
  int bf = blockIdx.x;
  int b = bf / NFEAT, f = bf - b*NFEAT;
  const float* base = xsrc + (size_t)b*LL*NFEAT + f;
  float m1 = g_m1[bf], s1 = g_s1[bf];
  float m2 = g_m2[bf], s2 = g_s2[bf];
  float lo1 = m1 - 4.f*s1, hi1 = m1 + 4.f*s1;
  float inv2 = 1.f / (s2 + 1e-6f);
  float sum = 0.f, sq = 0.f;
  for (int t = threadIdx.x; t < PP; t += blockDim.x) {
    float v = base[(size_t)t*NFEAT];
    if (mode >= 1) v = fminf(fmaxf(v, lo1), hi1);
    if (mode >= 2) v = (v - m2) * inv2;
    sum += v; sq += v*v;
  }
  sum = blockReduceSum(sum);
  sq  = blockReduceSum(sq);
  if (threadIdx.x == 0) {
    float m = sum * (1.f/PP);
    float var = sq * (1.f/PP) - m*m;
    float s = sqrtf(fmaxf(var, 0.f));
    if (mode == 0)      { g_m1[bf] = m; g_s1[bf] = s; }
    else if (mode == 1) { g_m2[bf] = m; g_s2[bf] = s; }
    else                { g_m3[bf] = m; g_s3[bf] = s; }
  }
}

// write normalized + padded input, row = l*BB + b
__global__ void __launch_bounds__(256) norm_write_kernel(const float* __restrict__ xsrc) {
  int idx = blockIdx.x * blockDim.x + threadIdx.x;
  if (idx >= LB*KPAD) return;
  int row = idx / KPAD, f = idx - row*KPAD;
  int l = row / BB, b = row - l*BB;
  float out = 0.f;
  if (f < NFEAT) {
    int bf = b*NFEAT + f;
    float v = xsrc[(size_t)b*LL*NFEAT + (size_t)l*NFEAT + f];
    float m1 = g_m1[bf], s1 = g_s1[bf];
    v = fminf(fmaxf(v, m1 - 4.f*s1), m1 + 4.f*s1);
    v = (v - g_m2[bf]) / (g_s2[bf] + 1e-6f);
    float m3 = g_m3[bf], s3 = g_s3[bf];
    v = fminf(fmaxf(v, m3 - 4.f*s3), m3 + 4.f*s3);
    if (!isfinite(v)) v = 0.f;
    out = v;
  }
  g_xn[idx] = out;
}

// rms-normalize encoded rows, add y encoding for first PP tokens, write (B,L,D)
__global__ void __launch_bounds__(256) encode_finish_kernel(const float* __restrict__ xeD,
    const float* __restrict__ ysrc, const float* __restrict__ yencW, const float* __restrict__ yencb) {
  int row = blockIdx.x;                 // l*BB + b
  int l = row / BB, b = row - l*BB;
  const float* xr = xeD + (size_t)row * DD;
  float v[4]; float sq = 0.f;
#pragma unroll
  for (int i = 0; i < 4; i++) { v[i] = xr[threadIdx.x + i*256]; sq += v[i]*v[i]; }
  float ms = blockReduceSum(sq) * (1.f/DD);
  float inv = 1.f / sqrtf(ms);
  bool addy = (l < PP);
  float yv = addy ? ysrc[(size_t)b*PP + l] : 0.f;
  float* dst = g_src + ((size_t)b*LL + l) * DD;
#pragma unroll
  for (int i = 0; i < 4; i++) {
    int c = threadIdx.x + i*256;
    float o = v[i] * inv;
    if (addy) o += yv * yencW[c] + yencb[c];
    dst[c] = o;
  }
}

// ---------------------------------------------------------------------------
// LayerNorm over D=1024 (block per row)
// ---------------------------------------------------------------------------
__global__ void __launch_bounds__(256) ln_kernel(const float* __restrict__ x,
    const float* __restrict__ gg, const float* __restrict__ bb, float* __restrict__ out) {
  int row = blockIdx.x;
  const float* xr = x + (size_t)row * DD;
  float v[4]; float s = 0.f;
#pragma unroll
  for (int i = 0; i < 4; i++) { v[i] = xr[threadIdx.x + i*256]; s += v[i]; }
  float m = blockReduceSum(s) * (1.f/DD);
  float d = 0.f;
#pragma unroll
  for (int i = 0; i < 4; i++) { float t = v[i]-m; d += t*t; }
  float var = blockReduceSum(d) * (1.f/DD);
  float r = rsqrtf(var + 1e-5f);
  float* orow = out + (size_t)row * DD;
#pragma unroll
  for (int i = 0; i < 4; i++) {
    int c = threadIdx.x + i*256;
    orow[c] = (v[i]-m)*r*gg[c] + bb[c];
  }
}

// per-head LN for q: row = b*LL + l, warp h handles head h; write (B,H,L,HD)
__global__ void __launch_bounds__(256) qln_kernel(const float* __restrict__ qraw,
    const float* __restrict__ gg, const float* __restrict__ bb, float* __restrict__ qh) {
  int row = blockIdx.x;
  int h = threadIdx.x >> 5, lane = threadIdx.x & 31;
  int b = row / LL, l = row - b*LL;
  const float* src = qraw + (size_t)row*DD + h*HDIM;
  float v[4]; float s = 0.f;
#pragma unroll
  for (int i = 0; i < 4; i++) { v[i] = src[lane + i*32]; s += v[i]; }
  float m = warpSum(s) * (1.f/HDIM);
  float d = 0.f;
#pragma unroll
  for (int i = 0; i < 4; i++) { float t = v[i]-m; d += t*t; }
  float var = warpSum(d) * (1.f/HDIM);
  float r = rsqrtf(var + 1e-5f);
  float* dst = qh + ((size_t)(b*HH + h)*LL + l) * HDIM;
#pragma unroll
  for (int i = 0; i < 4; i++) {
    int c = lane + i*32;
    dst[c] = (v[i]-m)*r*gg[c] + bb[c];
  }
}

// per-head LN for k + copy v: row = b*PP + t; write (B,H,P,HD)
__global__ void __launch_bounds__(256) klnv_kernel(const float* __restrict__ kv,
    const float* __restrict__ gg, const float* __restrict__ bb,
    float* __restrict__ kh, float* __restrict__ vh) {
  int row = blockIdx.x;
  int h = threadIdx.x >> 5, lane = threadIdx.x & 31;
  int b = row / PP, t = row - b*PP;
  const float* kp = kv + (size_t)row*2*DD + h*HDIM;
  const float* vp = kp + DD;
  float v[4]; float s = 0.f;
#pragma unroll
  for (int i = 0; i < 4; i++) { v[i] = kp[lane + i*32]; s += v[i]; }
  float m = warpSum(s) * (1.f/HDIM);
  float d = 0.f;
#pragma unroll
  for (int i = 0; i < 4; i++) { float t2 = v[i]-m; d += t2*t2; }
  float var = warpSum(d) * (1.f/HDIM);
  float r = rsqrtf(var + 1e-5f);
  size_t base = ((size_t)(b*HH + h)*PP + t) * HDIM;
#pragma unroll
  for (int i = 0; i < 4; i++) {
    int c = lane + i*32;
    kh[base + c] = (v[i]-m)*r*gg[c] + bb[c];
    vh[base + c] = vp[c];
  }
}

// softmax over last dim (PP=1024), in place
__global__ void __launch_bounds__(256) softmax_kernel(float* __restrict__ x) {
  float* xr = x + (size_t)blockIdx.x * PP;
  float v[4];
  float mx = -3.4e38f;
#pragma unroll
  for (int i = 0; i < 4; i++) { v[i] = xr[threadIdx.x + i*256]; mx = fmaxf(mx, v[i]); }
  mx = blockReduceMax(mx);
  float s = 0.f;
#pragma unroll
  for (int i = 0; i < 4; i++) { v[i] = expf(v[i] - mx); s += v[i]; }
  float tot = blockReduceSum(s);
  float inv = 1.f / tot;
#pragma unroll
  for (int i = 0; i < 4; i++) xr[threadIdx.x + i*256] = v[i] * inv;
}

// ---------------------------------------------------------------------------
// Generic batched SGEMM: C = act(alpha * A@B(^T) + bias) [+= C]
// Tiles 128x128x16, 256 threads, 8x8 per thread. Row-major everywhere.
// batch index bz -> (bo, bi) = (bz/inner, bz%inner), two-level strides.
// Requires: M%128==0, N%128==0, K%16==0 (A zero-padded in K), kGuard = valid
// B rows for the non-transposed loader.
// ---------------------------------------------------------------------------
template<bool TRANSB, bool ACT, bool HASBIAS, bool ACCUM>
__global__ void __launch_bounds__(256, 2) sgemm_kernel(
    const float* __restrict__ A, const float* __restrict__ B, float* __restrict__ C,
    const float* __restrict__ bias,
    int K, int kGuard, int lda, int ldb, int ldc, int inner,
    long long aSO, long long aSI, long long bSO, long long bSI,
    long long cSO, long long cSI, float alpha)
{
  __shared__ float As[16][128];
  __shared__ float Bs[16][128];

  int bz = blockIdx.z;
  int bo = bz / inner, bi = bz - bo*inner;
  A += bo*aSO + bi*aSI;
  B += bo*bSO + bi*bSI;
  C += bo*cSO + bi*cSI;

  const int tid = threadIdx.x;
  const int row0 = blockIdx.y * 128;
  const int col0 = blockIdx.x * 128;
  const int tx = tid & 15, ty = tid >> 4;
  const int tm0 = ty*8, tn0 = tx*8;

  float acc[8][8];
#pragma unroll
  for (int i = 0; i < 8; i++)
#pragma unroll
    for (int j = 0; j < 8; j++) acc[i][j] = 0.f;

  for (int k0 = 0; k0 < K; k0 += 16) {
#pragma unroll
    for (int u = 0; u < 2; u++) {
      int f = tid + u*256;
      int r = f >> 2, c4 = (f & 3) << 2;
      float4 va = *reinterpret_cast<const float4*>(A + (size_t)(row0 + r)*lda + (k0 + c4));
      As[c4+0][r] = va.x; As[c4+1][r] = va.y; As[c4+2][r] = va.z; As[c4+3][r] = va.w;
    }
    if (TRANSB) {
#pragma unroll
      for (int u = 0; u < 2; u++) {
        int f = tid + u*256;
        int n = f >> 2, k4 = (f & 3) << 2;
        float4 vb = *reinterpret_cast<const float4*>(B + (size_t)(col0 + n)*ldb + (k0 + k4));
        Bs[k4+0][n] = vb.x; Bs[k4+1][n] = vb.y; Bs[k4+2][n] = vb.z; Bs[k4+3][n] = vb.w;
      }
    } else {
#pragma unroll
      for (int u = 0; u < 2; u++) {
        int f = tid + u*256;
        int kk = f >> 5, n4 = (f & 31) << 2;
        float4 vb = make_float4(0.f, 0.f, 0.f, 0.f);
        if (k0 + kk < kGuard)
          vb = *reinterpret_cast<const float4*>(B + (size_t)(k0 + kk)*ldb + (col0 + n4));
        *reinterpret_cast<float4*>(&Bs[kk][n4]) = vb;
      }
    }
    __syncthreads();
#pragma unroll
    for (int kk = 0; kk < 16; kk++) {
      float4 a0 = *reinterpret_cast<const float4*>(&As[kk][tm0]);
      float4 a1 = *reinterpret_cast<const float4*>(&As[kk][tm0+4]);
      float4 b0 = *reinterpret_cast<const float4*>(&Bs[kk][tn0]);
      float4 b1 = *reinterpret_cast<const float4*>(&Bs[kk][tn0+4]);
      float ra[8] = {a0.x,a0.y,a0.z,a0.w,a1.x,a1.y,a1.z,a1.w};
      float rb[8] = {b0.x,b0.y,b0.z,b0.w,b1.x,b1.y,b1.z,b1.w};
#pragma unroll
      for (int i = 0; i < 8; i++)
#pragma unroll
        for (int j = 0; j < 8; j++)
          acc[i][j] = fmaf(ra[i], rb[j], acc[i][j]);
    }
    __syncthreads();
  }

#pragma unroll
  for (int i = 0; i < 8; i++) {
    float* crow = C + (size_t)(row0 + tm0 + i)*ldc + (col0 + tn0);
#pragma unroll
    for (int j = 0; j < 8; j += 4) {
      float4 v;
      v.x = alpha*acc[i][j+0]; v.y = alpha*acc[i][j+1];
      v.z = alpha*acc[i][j+2]; v.w = alpha*acc[i][j+3];
      if (HASBIAS) {
        float4 bbv = *reinterpret_cast<const float4*>(bias + col0 + tn0 + j);
        v.x += bbv.x; v.y += bbv.y; v.z += bbv.z; v.w += bbv.w;
      }
      if (ACT) { v.x = gelu_f(v.x); v.y = gelu_f(v.y); v.z = gelu_f(v.z); v.w = gelu_f(v.w); }
      if (ACCUM) {
        float4 o = *reinterpret_cast<const float4*>(crow + j);
        v.x += o.x; v.y += o.y; v.z += o.z; v.w += o.w;
      }
      *reinterpret_cast<float4*>(crow + j) = v;
    }
  }
}

// ---------------------------------------------------------------------------
// Head second GEMM: tiny N=11, only first 10 outputs, transposed write.
// Block per (b, t) row of hbuf; out[(t*BB + b)*NOUTD + o]
// ---------------------------------------------------------------------------
__global__ void __launch_bounds__(256) head2_kernel(const float* __restrict__ hbuf,
    const float* __restrict__ W2, const float* __restrict__ b2, float* __restrict__ out) {
  int idx = blockIdx.x;                 // b*PP + t
  int b = idx / PP, t = idx - b*PP;
  const float* hr = hbuf + (size_t)idx * NHID;
  float acc[NOUTD];
#pragma unroll
  for (int o = 0; o < NOUTD; o++) acc[o] = 0.f;
  for (int k = threadIdx.x; k < NHID; k += 256) {
    float v = hr[k];
    const float* w = W2 + (size_t)k * (NOUTD + 1);
#pragma unroll
    for (int o = 0; o < NOUTD; o++) acc[o] += v * w[o];
  }
  __shared__ float sm[8][NOUTD];
  int lane = threadIdx.x & 31, wid = threadIdx.x >> 5;
#pragma unroll
  for (int o = 0; o < NOUTD; o++) acc[o] = warpSum(acc[o]);
  if (lane == 0) {
#pragma unroll
    for (int o = 0; o < NOUTD; o++) sm[wid][o] = acc[o];
  }
  __syncthreads();
  if (threadIdx.x < NOUTD) {
    float s = 0.f;
#pragma unroll
    for (int w = 0; w < 8; w++) s += sm[w][threadIdx.x];
    out[((size_t)t*BB + b)*NOUTD + threadIdx.x] = s + b2[threadIdx.x];
  }
}

// ---------------------------------------------------------------------------
// Orchestration
// ---------------------------------------------------------------------------
extern "C" void kernel_launch(void* const* d_in, const int* in_sizes, int n_in,
                              void* d_out, int out_size) {
  (void)in_sizes; (void)n_in; (void)out_size;
  const float* x_src = (const float*)d_in[0];
  const float* y_src = (const float*)d_in[1];
  const float* enc_W = (const float*)d_in[2];
  const float* enc_b = (const float*)d_in[3];
  const float* yenc_W = (const float*)d_in[4];
  const float* yenc_b = (const float*)d_in[5];
  const float* Wq    = (const float*)d_in[6];
  const float* Wkv   = (const float*)d_in[7];
  const float* Wout  = (const float*)d_in[8];
  const float* an_g  = (const float*)d_in[9];
  const float* an_b  = (const float*)d_in[10];
  const float* qn_g  = (const float*)d_in[11];
  const float* qn_b  = (const float*)d_in[12];
  const float* kn_g  = (const float*)d_in[13];
  const float* kn_b  = (const float*)d_in[14];
  const float* fn_g  = (const float*)d_in[15];
  const float* fn_b  = (const float*)d_in[16];
  const float* ffW1  = (const float*)d_in[17];
  const float* ffb1  = (const float*)d_in[18];
  const float* ffW2  = (const float*)d_in[19];
  const float* ffb2  = (const float*)d_in[20];
  const float* hW1   = (const float*)d_in[21];
  const float* hb1   = (const float*)d_in[22];
  const float* hW2   = (const float*)d_in[23];
  const float* hb2   = (const float*)d_in[24];
  float* out = (float*)d_out;

  float *p_xn, *p_src, *p_h, *p_tmp, *p_kv, *p_qh, *p_kh, *p_vh, *p_logits, *p_ff;
  cudaGetSymbolAddress((void**)&p_xn, g_xn);
  cudaGetSymbolAddress((void**)&p_src, g_src);
  cudaGetSymbolAddress((void**)&p_h, g_h);
  cudaGetSymbolAddress((void**)&p_tmp, g_tmp);
  cudaGetSymbolAddress((void**)&p_kv, g_kv);
  cudaGetSymbolAddress((void**)&p_qh, g_qh);
  cudaGetSymbolAddress((void**)&p_kh, g_kh);
  cudaGetSymbolAddress((void**)&p_vh, g_vh);
  cudaGetSymbolAddress((void**)&p_logits, g_logits);
  cudaGetSymbolAddress((void**)&p_ff, g_ff);

  const float qk_scale = 0.08838834764831845f;  // 1/sqrt(HD)

  // --- preprocessing: 3 stats passes + normalized padded write ---
  colstats_kernel<<<BB*NFEAT, 256>>>(x_src, 0);
  colstats_kernel<<<BB*NFEAT, 256>>>(x_src, 1);
  colstats_kernel<<<BB*NFEAT, 256>>>(x_src, 2);
  norm_write_kernel<<<(LB*KPAD + 255)/256, 256>>>(x_src);

  // --- encoder: xn(8192x112) @ enc_W(100x1024) + bias -> tmp ---
  sgemm_kernel<false,false,true,false><<<dim3(DD/128, LB/128, 1), 256>>>(
      p_xn, enc_W, p_tmp, enc_b,
      KPAD, NFEAT, KPAD, DD, DD, 1, 0,0,0,0,0,0, 1.f);
  encode_finish_kernel<<<LB, 256>>>(p_tmp, y_src, yenc_W, yenc_b);

  for (int i = 0; i < NLAYERS; i++) {
    // attention block
    ln_kernel<<<LB, 256>>>(p_src, an_g + i*DD, an_b + i*DD, p_h);
    // q = h @ Wq  (8192x1024 @ 1024x1024) -> tmp
    sgemm_kernel<false,false,false,false><<<dim3(DD/128, LB/128, 1), 256>>>(
        p_h, Wq + (size_t)i*DD*DD, p_tmp, nullptr,
        DD, DD, DD, DD, DD, 1, 0,0,0,0,0,0, 1.f);
    // kv = h[:, :P] @ Wkv, batched over b
    sgemm_kernel<false,false,false,false><<<dim3(2*DD/128, PP/128, BB), 256>>>(
        p_h, Wkv + (size_t)i*DD*2*DD, p_kv, nullptr,
        DD, DD, DD, 2*DD, 2*DD, 1,
        (long long)LL*DD, 0, 0, 0, (long long)PP*2*DD, 0, 1.f);
    qln_kernel<<<LB, 256>>>(p_tmp, qn_g + i*HDIM, qn_b + i*HDIM, p_qh);
    klnv_kernel<<<BB*PP, 256>>>(p_kv, kn_g + i*HDIM, kn_b + i*HDIM, p_kh, p_vh);
    // logits = scale * q @ k^T, batched over (b,h)
    sgemm_kernel<true,false,false,false><<<dim3(PP/128, LL/128, BB*HH), 256>>>(
        p_qh, p_kh, p_logits, nullptr,
        HDIM, HDIM, HDIM, HDIM, PP, 1,
        (long long)LL*HDIM, 0, (long long)PP*HDIM, 0, (long long)LL*PP, 0, qk_scale);
    softmax_kernel<<<BB*HH*LL, 256>>>(p_logits);
    // attn = probs @ v -> tmp in (B,L,H,HD) = (B,L,D) layout
    sgemm_kernel<false,false,false,false><<<dim3(HDIM/128, LL/128, BB*HH), 256>>>(
        p_logits, p_vh, p_tmp, nullptr,
        PP, PP, PP, HDIM, DD, HH,
        (long long)HH*LL*PP, (long long)LL*PP,
        (long long)HH*PP*HDIM, (long long)PP*HDIM,
        (long long)LL*DD, (long long)HDIM, 1.f);
    // src += attn @ Wout
    sgemm_kernel<false,false,false,true><<<dim3(DD/128, LB/128, 1), 256>>>(
        p_tmp, Wout + (size_t)i*DD*DD, p_src, nullptr,
        DD, DD, DD, DD, DD, 1, 0,0,0,0,0,0, 1.f);
    // FFN block
    ln_kernel<<<LB, 256>>>(p_src, fn_g + i*DD, fn_b + i*DD, p_h);
    sgemm_kernel<false,true,true,false><<<dim3(NHID/128, LB/128, 1), 256>>>(
        p_h, ffW1 + (size_t)i*DD*NHID, p_ff, ffb1 + (size_t)i*NHID,
        DD, DD, DD, NHID, NHID, 1, 0,0,0,0,0,0, 1.f);
    sgemm_kernel<false,false,true,true><<<dim3(DD/128, LB/128, 1), 256>>>(
        p_ff, ffW2 + (size_t)i*NHID*DD, p_src, ffb2 + (size_t)i*DD,
        NHID, NHID, NHID, DD, DD, 1, 0,0,0,0,0,0, 1.f);
  }

  // head: only tokens [P, L) needed; batched over b
  sgemm_kernel<false,true,true,false><<<dim3(NHID/128, PP/128, BB), 256>>>(
      p_src + (size_t)PP*DD, hW1, p_ff, hb1,
      DD, DD, DD, NHID, NHID, 1,
      (long long)LL*DD, 0, 0, 0, (long long)PP*NHID, 0, 1.f);
  head2_kernel<<<BB*PP, 256>>>(p_ff, hW2, hb2, out);
}

// round 3
// speedup vs baseline: 2.1980x; 2.1980x over previous
#include <cuda_runtime.h>
#include <cuda_bf16.h>
#include <cstdint>
#include <cstddef>
#include <math.h>

// ---------------------------------------------------------------------------
// Problem constants
// ---------------------------------------------------------------------------
#define BB     4
#define LL     2048
#define PP     1024
#define NFEAT  100
#define DD     1024
#define HH     8
#define HDIM   128
#define NHID   4096
#define NLAYERS 3
#define NOUTD  10
#define LB     (LL*BB)
#define KPAD   112

typedef __nv_bfloat16 bf16;

// ---------------------------------------------------------------------------
// Scratch (device globals)
// ---------------------------------------------------------------------------
__device__ float g_m1[BB*NFEAT], g_s1[BB*NFEAT];
__device__ float g_m2[BB*NFEAT], g_s2[BB*NFEAT];
__device__ float g_m3[BB*NFEAT], g_s3[BB*NFEAT];
__device__ __align__(256) float g_xn[(size_t)LB*KPAD];
__device__ __align__(256) float g_src[(size_t)LB*DD];
__device__ __align__(256) float g_tmp[(size_t)LB*DD];     // enc out / q raw / kv
__device__ __align__(256) float g_vh [(size_t)BB*HH*PP*HDIM];
__device__ __align__(256) float g_logits[(size_t)BB*HH*LL*PP];

// bf16 split activation buffers
__device__ __align__(256) bf16 g_ah[(size_t)LB*DD];
__device__ __align__(256) bf16 g_al[(size_t)LB*DD];
__device__ __align__(256) bf16 g_qhh[(size_t)BB*HH*LL*HDIM];
__device__ __align__(256) bf16 g_qhl[(size_t)BB*HH*LL*HDIM];
__device__ __align__(256) bf16 g_khh[(size_t)BB*HH*PP*HDIM];
__device__ __align__(256) bf16 g_khl[(size_t)BB*HH*PP*HDIM];
__device__ __align__(256) bf16 g_vth[(size_t)BB*HH*HDIM*PP];
__device__ __align__(256) bf16 g_vtl[(size_t)BB*HH*HDIM*PP];
__device__ __align__(256) bf16 g_ph [(size_t)BB*HH*LL*PP];
__device__ __align__(256) bf16 g_pl [(size_t)BB*HH*LL*PP];
__device__ __align__(256) bf16 g_ffh[(size_t)LB*NHID];
__device__ __align__(256) bf16 g_ffl[(size_t)LB*NHID];

// bf16 split transposed weights
__device__ __align__(256) bf16 g_WqTh [(size_t)NLAYERS*DD*DD];
__device__ __align__(256) bf16 g_WqTl [(size_t)NLAYERS*DD*DD];
__device__ __align__(256) bf16 g_WkvTh[(size_t)NLAYERS*2*DD*DD];
__device__ __align__(256) bf16 g_WkvTl[(size_t)NLAYERS*2*DD*DD];
__device__ __align__(256) bf16 g_WoTh [(size_t)NLAYERS*DD*DD];
__device__ __align__(256) bf16 g_WoTl [(size_t)NLAYERS*DD*DD];
__device__ __align__(256) bf16 g_W1Th [(size_t)NLAYERS*NHID*DD];
__device__ __align__(256) bf16 g_W1Tl [(size_t)NLAYERS*NHID*DD];
__device__ __align__(256) bf16 g_W2Th [(size_t)NLAYERS*DD*NHID];
__device__ __align__(256) bf16 g_W2Tl [(size_t)NLAYERS*DD*NHID];
__device__ __align__(256) bf16 g_hW1Th[(size_t)NHID*DD];
__device__ __align__(256) bf16 g_hW1Tl[(size_t)NHID*DD];

// ---------------------------------------------------------------------------
// Reductions / helpers
// ---------------------------------------------------------------------------
__device__ __forceinline__ float warpSum(float v) {
#pragma unroll
  for (int o = 16; o > 0; o >>= 1) v += __shfl_xor_sync(0xffffffffu, v, o);
  return v;
}

__device__ __forceinline__ float blockReduceSum(float v) {
  __shared__ float sh[32];
  int lane = threadIdx.x & 31, wid = threadIdx.x >> 5;
  v = warpSum(v);
  if (lane == 0) sh[wid] = v;
  __syncthreads();
  int nw = (blockDim.x + 31) >> 5;
  v = (threadIdx.x < nw) ? sh[threadIdx.x] : 0.f;
  if (wid == 0) { v = warpSum(v); if (lane == 0) sh[0] = v; }
  __syncthreads();
  float r = sh[0];
  __syncthreads();
  return r;
}

__device__ __forceinline__ float blockReduceMax(float v) {
  __shared__ float sh[32];
  int lane = threadIdx.x & 31, wid = threadIdx.x >> 5;
#pragma unroll
  for (int o = 16; o > 0; o >>= 1) v = fmaxf(v, __shfl_xor_sync(0xffffffffu, v, o));
  if (lane == 0) sh[wid] = v;
  __syncthreads();
  int nw = (blockDim.x + 31) >> 5;
  v = (threadIdx.x < nw) ? sh[threadIdx.x] : -3.4e38f;
  if (wid == 0) {
#pragma unroll
    for (int o = 16; o > 0; o >>= 1) v = fmaxf(v, __shfl_xor_sync(0xffffffffu, v, o));
    if (lane == 0) sh[0] = v;
  }
  __syncthreads();
  float r = sh[0];
  __syncthreads();
  return r;
}

__device__ __forceinline__ float gelu_f(float x) {
  return 0.5f * x * (1.0f + erff(x * 0.7071067811865475f));
}

__device__ __forceinline__ void split2(float v, bf16& h, bf16& l) {
  h = __float2bfloat16_rn(v);
  l = __float2bfloat16_rn(v - __bfloat162float(h));
}

__device__ __forceinline__ unsigned s2u(const void* p) {
  return (unsigned)__cvta_generic_to_shared(p);
}

__device__ __forceinline__ void cpa16(unsigned s, const void* g) {
  asm volatile("cp.async.cg.shared.global [%0], [%1], 16;\n" :: "r"(s), "l"(g));
}

__device__ __forceinline__ void ldsm4(unsigned* r, unsigned addr) {
  asm volatile("ldmatrix.sync.aligned.m8n8.x4.shared.b16 {%0,%1,%2,%3}, [%4];\n"
    : "=r"(r[0]), "=r"(r[1]), "=r"(r[2]), "=r"(r[3]) : "r"(addr));
}

__device__ __forceinline__ void mma16816(float* c, const unsigned* a, const unsigned* b) {
  asm volatile("mma.sync.aligned.m16n8k16.row.col.f32.bf16.bf16.f32 "
    "{%0,%1,%2,%3}, {%4,%5,%6,%7}, {%8,%9}, {%0,%1,%2,%3};\n"
    : "+f"(c[0]), "+f"(c[1]), "+f"(c[2]), "+f"(c[3])
    : "r"(a[0]), "r"(a[1]), "r"(a[2]), "r"(a[3]), "r"(b[0]), "r"(b[1]));
}

// ---------------------------------------------------------------------------
// Preprocessing
// ---------------------------------------------------------------------------
__global__ void __launch_bounds__(256) colstats_kernel(const float* __restrict__ xsrc, int mode) {
  int bf = blockIdx.x;
  int b = bf / NFEAT, f = bf - b*NFEAT;
  const float* base = xsrc + (size_t)b*LL*NFEAT + f;
  float m1 = g_m1[bf], s1 = g_s1[bf];
  float m2 = g_m2[bf], s2 = g_s2[bf];
  float lo1 = m1 - 4.f*s1, hi1 = m1 + 4.f*s1;
  float inv2 = 1.f / (s2 + 1e-6f);
  float sum = 0.f, sq = 0.f;
  for (int t = threadIdx.x; t < PP; t += blockDim.x) {
    float v = base[(size_t)t*NFEAT];
    if (mode >= 1) v = fminf(fmaxf(v, lo1), hi1);
    if (mode >= 2) v = (v - m2) * inv2;
    sum += v; sq += v*v;
  }
  sum = blockReduceSum(sum);
  sq  = blockReduceSum(sq);
  if (threadIdx.x == 0) {
    float m = sum * (1.f/PP);
    float var = sq * (1.f/PP) - m*m;
    float s = sqrtf(fmaxf(var, 0.f));
    if (mode == 0)      { g_m1[bf] = m; g_s1[bf] = s; }
    else if (mode == 1) { g_m2[bf] = m; g_s2[bf] = s; }
    else                { g_m3[bf] = m; g_s3[bf] = s; }
  }
}

__global__ void __launch_bounds__(256) norm_write_kernel(const float* __restrict__ xsrc) {
  int idx = blockIdx.x * blockDim.x + threadIdx.x;
  if (idx >= LB*KPAD) return;
  int row = idx / KPAD, f = idx - row*KPAD;
  int l = row / BB, b = row - l*BB;
  float out = 0.f;
  if (f < NFEAT) {
    int bf = b*NFEAT + f;
    float v = xsrc[(size_t)b*LL*NFEAT + (size_t)l*NFEAT + f];
    float m1 = g_m1[bf], s1 = g_s1[bf];
    v = fminf(fmaxf(v, m1 - 4.f*s1), m1 + 4.f*s1);
    v = (v - g_m2[bf]) / (g_s2[bf] + 1e-6f);
    float m3 = g_m3[bf], s3 = g_s3[bf];
    v = fminf(fmaxf(v, m3 - 4.f*s3), m3 + 4.f*s3);
    if (!isfinite(v)) v = 0.f;
    out = v;
  }
  g_xn[idx] = out;
}

__global__ void __launch_bounds__(256) encode_finish_kernel(const float* __restrict__ xeD,
    const float* __restrict__ ysrc, const float* __restrict__ yencW, const float* __restrict__ yencb) {
  int row = blockIdx.x;                 // l*BB + b
  int l = row / BB, b = row - l*BB;
  const float* xr = xeD + (size_t)row * DD;
  float v[4]; float sq = 0.f;
#pragma unroll
  for (int i = 0; i < 4; i++) { v[i] = xr[threadIdx.x + i*256]; sq += v[i]*v[i]; }
  float ms = blockReduceSum(sq) * (1.f/DD);
  float inv = 1.f / sqrtf(ms);
  bool addy = (l < PP);
  float yv = addy ? ysrc[(size_t)b*PP + l] : 0.f;
  float* dst = g_src + ((size_t)b*LL + l) * DD;
#pragma unroll
  for (int i = 0; i < 4; i++) {
    int c = threadIdx.x + i*256;
    float o = v[i] * inv;
    if (addy) o += yv * yencW[c] + yencb[c];
    dst[c] = o;
  }
}

// ---------------------------------------------------------------------------
// LayerNorm (D) with split bf16 output
// ---------------------------------------------------------------------------
__global__ void __launch_bounds__(256) ln_split_kernel(const float* __restrict__ x,
    const float* __restrict__ gg, const float* __restrict__ bbp,
    bf16* __restrict__ oh, bf16* __restrict__ ol) {
  int row = blockIdx.x;
  const float* xr = x + (size_t)row * DD;
  float v[4]; float s = 0.f;
#pragma unroll
  for (int i = 0; i < 4; i++) { v[i] = xr[threadIdx.x + i*256]; s += v[i]; }
  float m = blockReduceSum(s) * (1.f/DD);
  float d = 0.f;
#pragma unroll
  for (int i = 0; i < 4; i++) { float t = v[i]-m; d += t*t; }
  float var = blockReduceSum(d) * (1.f/DD);
  float r = rsqrtf(var + 1e-5f);
#pragma unroll
  for (int i = 0; i < 4; i++) {
    int c = threadIdx.x + i*256;
    float o = (v[i]-m)*r*gg[c] + bbp[c];
    bf16 h, l; split2(o, h, l);
    oh[(size_t)row*DD + c] = h;
    ol[(size_t)row*DD + c] = l;
  }
}

// q per-head LN -> split (B,H,L,HD)
__global__ void __launch_bounds__(256) qln_split_kernel(const float* __restrict__ qraw,
    const float* __restrict__ gg, const float* __restrict__ bbp,
    bf16* __restrict__ qh, bf16* __restrict__ ql) {
  int row = blockIdx.x;
  int h = threadIdx.x >> 5, lane = threadIdx.x & 31;
  int b = row / LL, l = row - b*LL;
  const float* src = qraw + (size_t)row*DD + h*HDIM;
  float v[4]; float s = 0.f;
#pragma unroll
  for (int i = 0; i < 4; i++) { v[i] = src[lane + i*32]; s += v[i]; }
  float m = warpSum(s) * (1.f/HDIM);
  float d = 0.f;
#pragma unroll
  for (int i = 0; i < 4; i++) { float t = v[i]-m; d += t*t; }
  float var = warpSum(d) * (1.f/HDIM);
  float r = rsqrtf(var + 1e-5f);
  size_t base = ((size_t)(b*HH + h)*LL + l) * HDIM;
#pragma unroll
  for (int i = 0; i < 4; i++) {
    int c = lane + i*32;
    float o = (v[i]-m)*r*gg[c] + bbp[c];
    bf16 hh, ll; split2(o, hh, ll);
    qh[base + c] = hh; ql[base + c] = ll;
  }
}

// k per-head LN -> split (B,H,P,HD); v copy fp32 (B,H,P,HD)
__global__ void __launch_bounds__(256) klnv_split_kernel(const float* __restrict__ kv,
    const float* __restrict__ gg, const float* __restrict__ bbp,
    bf16* __restrict__ kh, bf16* __restrict__ kl, float* __restrict__ vh) {
  int row = blockIdx.x;
  int h = threadIdx.x >> 5, lane = threadIdx.x & 31;
  int b = row / PP, t = row - b*PP;
  const float* kp = kv + (size_t)row*2*DD + h*HDIM;
  const float* vp = kp + DD;
  float v[4]; float s = 0.f;
#pragma unroll
  for (int i = 0; i < 4; i++) { v[i] = kp[lane + i*32]; s += v[i]; }
  float m = warpSum(s) * (1.f/HDIM);
  float d = 0.f;
#pragma unroll
  for (int i = 0; i < 4; i++) { float t2 = v[i]-m; d += t2*t2; }
  float var = warpSum(d) * (1.f/HDIM);
  float r = rsqrtf(var + 1e-5f);
  size_t base = ((size_t)(b*HH + h)*PP + t) * HDIM;
#pragma unroll
  for (int i = 0; i < 4; i++) {
    int c = lane + i*32;
    float o = (v[i]-m)*r*gg[c] + bbp[c];
    bf16 hh, ll; split2(o, hh, ll);
    kh[base + c] = hh; kl[base + c] = ll;
    vh[base + c] = vp[c];
  }
}

// softmax over PP, write split probs
__global__ void __launch_bounds__(256) softmax_split_kernel(const float* __restrict__ x,
    bf16* __restrict__ ph, bf16* __restrict__ pl) {
  const float* xr = x + (size_t)blockIdx.x * PP;
  float v[4];
  float mx = -3.4e38f;
#pragma unroll
  for (int i = 0; i < 4; i++) { v[i] = xr[threadIdx.x + i*256]; mx = fmaxf(mx, v[i]); }
  mx = blockReduceMax(mx);
  float s = 0.f;
#pragma unroll
  for (int i = 0; i < 4; i++) { v[i] = expf(v[i] - mx); s += v[i]; }
  float tot = blockReduceSum(s);
  float inv = 1.f / tot;
  size_t base = (size_t)blockIdx.x * PP;
#pragma unroll
  for (int i = 0; i < 4; i++) {
    float p = v[i] * inv;
    bf16 h, l; split2(p, h, l);
    int c = threadIdx.x + i*256;
    ph[base + c] = h; pl[base + c] = l;
  }
}

// elementwise split
__global__ void __launch_bounds__(256) split_rows_kernel(const float* __restrict__ x,
    bf16* __restrict__ h, bf16* __restrict__ l, int n) {
  int idx = blockIdx.x * blockDim.x + threadIdx.x;
  if (idx >= n) return;
  bf16 hh, ll; split2(x[idx], hh, ll);
  h[idx] = hh; l[idx] = ll;
}

// transpose + split: src fp32 [R][C] -> dst [C][R] bf16 hi/lo. grid (C/32, R/32, batch)
__global__ void __launch_bounds__(256) transpose_split_kernel(const float* __restrict__ src,
    bf16* __restrict__ dh, bf16* __restrict__ dl, int R, int C,
    long long sStride, long long dStride) {
  __shared__ float t[32][33];
  int z = blockIdx.z;
  src += (long long)z * sStride;
  dh  += (long long)z * dStride;
  dl  += (long long)z * dStride;
  int c0 = blockIdx.x * 32, r0 = blockIdx.y * 32;
  int tx = threadIdx.x & 31, ty = threadIdx.x >> 5;   // 32x8
#pragma unroll
  for (int j = ty; j < 32; j += 8)
    t[j][tx] = src[(size_t)(r0+j)*C + c0 + tx];
  __syncthreads();
#pragma unroll
  for (int j = ty; j < 32; j += 8) {
    float v = t[tx][j];
    bf16 hh, ll; split2(v, hh, ll);
    size_t off = (size_t)(c0+j)*R + r0 + tx;
    dh[off] = hh; dl[off] = ll;
  }
}

// ---------------------------------------------------------------------------
// fp32 SGEMM (encoder only; K=112 zero-padded A)
// ---------------------------------------------------------------------------
template<bool HASBIAS>
__global__ void __launch_bounds__(256, 2) sgemm_kernel(
    const float* __restrict__ A, const float* __restrict__ B, float* __restrict__ C,
    const float* __restrict__ bias, int K, int kGuard, int lda, int ldb, int ldc)
{
  __shared__ float As[16][128];
  __shared__ float Bs[16][128];
  const int tid = threadIdx.x;
  const int row0 = blockIdx.y * 128;
  const int col0 = blockIdx.x * 128;
  const int tx = tid & 15, ty = tid >> 4;
  const int tm0 = ty*8, tn0 = tx*8;
  float acc[8][8];
#pragma unroll
  for (int i = 0; i < 8; i++)
#pragma unroll
    for (int j = 0; j < 8; j++) acc[i][j] = 0.f;
  for (int k0 = 0; k0 < K; k0 += 16) {
#pragma unroll
    for (int u = 0; u < 2; u++) {
      int f = tid + u*256;
      int r = f >> 2, c4 = (f & 3) << 2;
      float4 va = *reinterpret_cast<const float4*>(A + (size_t)(row0 + r)*lda + (k0 + c4));
      As[c4+0][r] = va.x; As[c4+1][r] = va.y; As[c4+2][r] = va.z; As[c4+3][r] = va.w;
    }
#pragma unroll
    for (int u = 0; u < 2; u++) {
      int f = tid + u*256;
      int kk = f >> 5, n4 = (f & 31) << 2;
      float4 vb = make_float4(0.f, 0.f, 0.f, 0.f);
      if (k0 + kk < kGuard)
        vb = *reinterpret_cast<const float4*>(B + (size_t)(k0 + kk)*ldb + (col0 + n4));
      *reinterpret_cast<float4*>(&Bs[kk][n4]) = vb;
    }
    __syncthreads();
#pragma unroll
    for (int kk = 0; kk < 16; kk++) {
      float4 a0 = *reinterpret_cast<const float4*>(&As[kk][tm0]);
      float4 a1 = *reinterpret_cast<const float4*>(&As[kk][tm0+4]);
      float4 b0 = *reinterpret_cast<const float4*>(&Bs[kk][tn0]);
      float4 b1 = *reinterpret_cast<const float4*>(&Bs[kk][tn0+4]);
      float ra[8] = {a0.x,a0.y,a0.z,a0.w,a1.x,a1.y,a1.z,a1.w};
      float rb[8] = {b0.x,b0.y,b0.z,b0.w,b1.x,b1.y,b1.z,b1.w};
#pragma unroll
      for (int i = 0; i < 8; i++)
#pragma unroll
        for (int j = 0; j < 8; j++)
          acc[i][j] = fmaf(ra[i], rb[j], acc[i][j]);
    }
    __syncthreads();
  }
#pragma unroll
  for (int i = 0; i < 8; i++) {
    float* crow = C + (size_t)(row0 + tm0 + i)*ldc + (col0 + tn0);
#pragma unroll
    for (int j = 0; j < 8; j += 4) {
      float4 v;
      v.x = acc[i][j+0]; v.y = acc[i][j+1]; v.z = acc[i][j+2]; v.w = acc[i][j+3];
      if (HASBIAS) {
        float4 bbv = *reinterpret_cast<const float4*>(bias + col0 + tn0 + j);
        v.x += bbv.x; v.y += bbv.y; v.z += bbv.z; v.w += bbv.w;
      }
      *reinterpret_cast<float4*>(crow + j) = v;
    }
  }
}

// ---------------------------------------------------------------------------
// Tensor-core GEMM (bf16x3 split): C = act(alpha*(Ah+Al)@(Bh+Bl)^T + bias)
// A: [M][K] hi/lo bf16 (lda), B: [N][K] hi/lo bf16 (ldb)  -- TN, k-contiguous
// OUTMODE: 0 = store fp32 C; 1 = C += (accum fp32); 2 = store split bf16 Ch/Cl
// Block 128x128, K-step 32, 2-stage cp.async pipeline. M,N mult of 128; K mult 32.
// ---------------------------------------------------------------------------
#define LDSROW 40
#define TILE_ELEMS (128*LDSROW)
#define STAGE_ELEMS (4*TILE_ELEMS)
#define MMA_SMEM_BYTES (2*STAGE_ELEMS*2)

template<bool ACT, bool HASBIAS, int OUTMODE>
__global__ void __launch_bounds__(256) mma_gemm_kernel(
    const bf16* __restrict__ Ah, const bf16* __restrict__ Al,
    const bf16* __restrict__ Bh, const bf16* __restrict__ Bl,
    float* __restrict__ C, bf16* __restrict__ Ch, bf16* __restrict__ Cl,
    const float* __restrict__ bias,
    int K, int lda, int ldb, int ldc, int inner,
    long long aSO, long long aSI, long long bSO, long long bSI,
    long long cSO, long long cSI, float alpha)
{
  extern __shared__ bf16 smbuf[];
  int bz = blockIdx.z;
  int bo = bz / inner, bi = bz - bo*inner;
  long long aoff = (long long)bo*aSO + (long long)bi*aSI;
  long long boff = (long long)bo*bSO + (long long)bi*bSI;
  long long coff = (long long)bo*cSO + (long long)bi*cSI;
  Ah += aoff; Al += aoff; Bh += boff; Bl += boff;

  const int tid = threadIdx.x;
  const int row0 = blockIdx.y * 128;
  const int col0 = blockIdx.x * 128;
  const int wid = tid >> 5, lane = tid & 31;
  const int wm = (wid & 3) * 32;
  const int wn = (wid >> 2) * 64;

  float acc[2][8][4];
#pragma unroll
  for (int mt = 0; mt < 2; mt++)
#pragma unroll
    for (int nt = 0; nt < 8; nt++)
#pragma unroll
      for (int q = 0; q < 4; q++) acc[mt][nt][q] = 0.f;

  // --- prologue: stage 0 ---
  {
    bf16* base = smbuf;
#pragma unroll
    for (int i = 0; i < 2; i++) {
      int c = tid + i*256;
      int r = c >> 2, kc = (c & 3) << 3;
      cpa16(s2u(base + 0*TILE_ELEMS + r*LDSROW + kc), Ah + (size_t)(row0+r)*lda + kc);
      cpa16(s2u(base + 1*TILE_ELEMS + r*LDSROW + kc), Al + (size_t)(row0+r)*lda + kc);
      cpa16(s2u(base + 2*TILE_ELEMS + r*LDSROW + kc), Bh + (size_t)(col0+r)*ldb + kc);
      cpa16(s2u(base + 3*TILE_ELEMS + r*LDSROW + kc), Bl + (size_t)(col0+r)*ldb + kc);
    }
    asm volatile("cp.async.commit_group;\n");
  }

  int s = 0;
  for (int k0 = 0; k0 < K; k0 += 32, s ^= 1) {
    asm volatile("cp.async.wait_group 0;\n");
    __syncthreads();
    if (k0 + 32 < K) {
      bf16* base = smbuf + (s^1)*STAGE_ELEMS;
      int kn = k0 + 32;
#pragma unroll
      for (int i = 0; i < 2; i++) {
        int c = tid + i*256;
        int r = c >> 2, kc = (c & 3) << 3;
        cpa16(s2u(base + 0*TILE_ELEMS + r*LDSROW + kc), Ah + (size_t)(row0+r)*lda + kn + kc);
        cpa16(s2u(base + 1*TILE_ELEMS + r*LDSROW + kc), Al + (size_t)(row0+r)*lda + kn + kc);
        cpa16(s2u(base + 2*TILE_ELEMS + r*LDSROW + kc), Bh + (size_t)(col0+r)*ldb + kn + kc);
        cpa16(s2u(base + 3*TILE_ELEMS + r*LDSROW + kc), Bl + (size_t)(col0+r)*ldb + kn + kc);
      }
      asm volatile("cp.async.commit_group;\n");
    }

    bf16* sAh = smbuf + s*STAGE_ELEMS;
    bf16* sAl = sAh + TILE_ELEMS;
    bf16* sBh = sAh + 2*TILE_ELEMS;
    bf16* sBl = sAh + 3*TILE_ELEMS;
    int arow = lane & 15;
    int khalf = (lane >> 4) << 3;

#pragma unroll
    for (int kk = 0; kk < 2; kk++) {
      int kof = kk*16 + khalf;
      unsigned ahf[2][4], alf[2][4], bfr[8][2];
#pragma unroll
      for (int mt = 0; mt < 2; mt++) {
        ldsm4(ahf[mt], s2u(sAh + (wm + mt*16 + arow)*LDSROW + kof));
        ldsm4(alf[mt], s2u(sAl + (wm + mt*16 + arow)*LDSROW + kof));
      }
      // B hi
#pragma unroll
      for (int np = 0; np < 4; np++) {
        unsigned t[4];
        ldsm4(t, s2u(sBh + (wn + np*16 + arow)*LDSROW + kof));
        bfr[2*np][0] = t[0]; bfr[2*np][1] = t[2];
        bfr[2*np+1][0] = t[1]; bfr[2*np+1][1] = t[3];
      }
#pragma unroll
      for (int mt = 0; mt < 2; mt++)
#pragma unroll
        for (int nt = 0; nt < 8; nt++) {
          mma16816(acc[mt][nt], ahf[mt], bfr[nt]);
          mma16816(acc[mt][nt], alf[mt], bfr[nt]);
        }
      // B lo (reuse regs)
#pragma unroll
      for (int np = 0; np < 4; np++) {
        unsigned t[4];
        ldsm4(t, s2u(sBl + (wn + np*16 + arow)*LDSROW + kof));
        bfr[2*np][0] = t[0]; bfr[2*np][1] = t[2];
        bfr[2*np+1][0] = t[1]; bfr[2*np+1][1] = t[3];
      }
#pragma unroll
      for (int mt = 0; mt < 2; mt++)
#pragma unroll
        for (int nt = 0; nt < 8; nt++)
          mma16816(acc[mt][nt], ahf[mt], bfr[nt]);
    }
  }

  // --- epilogue ---
  int rb = row0 + wm + (lane >> 2);
  int cb = col0 + wn + (lane & 3)*2;
#pragma unroll
  for (int mt = 0; mt < 2; mt++) {
#pragma unroll
    for (int nt = 0; nt < 8; nt++) {
#pragma unroll
      for (int h2 = 0; h2 < 2; h2++) {
        int r = rb + mt*16 + h2*8;
        int cc = cb + nt*8;
        float v0 = alpha * acc[mt][nt][h2*2+0];
        float v1 = alpha * acc[mt][nt][h2*2+1];
        if (HASBIAS) { v0 += bias[cc]; v1 += bias[cc+1]; }
        if (ACT) { v0 = gelu_f(v0); v1 = gelu_f(v1); }
        long long off = coff + (long long)r*ldc + cc;
        if (OUTMODE == 0) {
          float2 o; o.x = v0; o.y = v1;
          *reinterpret_cast<float2*>(C + off) = o;
        } else if (OUTMODE == 1) {
          float2 o = *reinterpret_cast<const float2*>(C + off);
          o.x += v0; o.y += v1;
          *reinterpret_cast<float2*>(C + off) = o;
        } else {
          bf16 h0, l0, h1, l1;
          split2(v0, h0, l0); split2(v1, h1, l1);
          __nv_bfloat162 phv; phv.x = h0; phv.y = h1;
          __nv_bfloat162 plv; plv.x = l0; plv.y = l1;
          *reinterpret_cast<__nv_bfloat162*>(Ch + off) = phv;
          *reinterpret_cast<__nv_bfloat162*>(Cl + off) = plv;
        }
      }
    }
  }
}

// ---------------------------------------------------------------------------
// Head second GEMM (reads split hidden)
// ---------------------------------------------------------------------------
__global__ void __launch_bounds__(256) head2_kernel(const bf16* __restrict__ hbh,
    const bf16* __restrict__ hbl, const float* __restrict__ W2,
    const float* __restrict__ b2, float* __restrict__ out) {
  int idx = blockIdx.x;                 // b*PP + t
  int b = idx / PP, t = idx - b*PP;
  const bf16* hh = hbh + (size_t)idx * NHID;
  const bf16* hl = hbl + (size_t)idx * NHID;
  float acc[NOUTD];
#pragma unroll
  for (int o = 0; o < NOUTD; o++) acc[o] = 0.f;
  for (int k = threadIdx.x; k < NHID; k += 256) {
    float v = __bfloat162float(hh[k]) + __bfloat162float(hl[k]);
    const float* w = W2 + (size_t)k * (NOUTD + 1);
#pragma unroll
    for (int o = 0; o < NOUTD; o++) acc[o] += v * w[o];
  }
  __shared__ float smr[8][NOUTD];
  int lane = threadIdx.x & 31, wid = threadIdx.x >> 5;
#pragma unroll
  for (int o = 0; o < NOUTD; o++) acc[o] = warpSum(acc[o]);
  if (lane == 0) {
#pragma unroll
    for (int o = 0; o < NOUTD; o++) smr[wid][o] = acc[o];
  }
  __syncthreads();
  if (threadIdx.x < NOUTD) {
    float sv = 0.f;
#pragma unroll
    for (int w = 0; w < 8; w++) sv += smr[w][threadIdx.x];
    out[((size_t)t*BB + b)*NOUTD + threadIdx.x] = sv + b2[threadIdx.x];
  }
}

// ---------------------------------------------------------------------------
// Orchestration
// ---------------------------------------------------------------------------
extern "C" void kernel_launch(void* const* d_in, const int* in_sizes, int n_in,
                              void* d_out, int out_size) {
  (void)in_sizes; (void)n_in; (void)out_size;
  const float* x_src = (const float*)d_in[0];
  const float* y_src = (const float*)d_in[1];
  const float* enc_W = (const float*)d_in[2];
  const float* enc_b = (const float*)d_in[3];
  const float* yenc_W = (const float*)d_in[4];
  const float* yenc_b = (const float*)d_in[5];
  const float* Wq    = (const float*)d_in[6];
  const float* Wkv   = (const float*)d_in[7];
  const float* Wout  = (const float*)d_in[8];
  const float* an_g  = (const float*)d_in[9];
  const float* an_b  = (const float*)d_in[10];
  const float* qn_g  = (const float*)d_in[11];
  const float* qn_b  = (const float*)d_in[12];
  const float* kn_g  = (const float*)d_in[13];
  const float* kn_b  = (const float*)d_in[14];
  const float* fn_g  = (const float*)d_in[15];
  const float* fn_b  = (const float*)d_in[16];
  const float* ffW1  = (const float*)d_in[17];
  const float* ffb1  = (const float*)d_in[18];
  const float* ffW2  = (const float*)d_in[19];
  const float* ffb2  = (const float*)d_in[20];
  const float* hW1   = (const float*)d_in[21];
  const float* hb1   = (const float*)d_in[22];
  const float* hW2   = (const float*)d_in[23];
  const float* hb2   = (const float*)d_in[24];
  float* out = (float*)d_out;

  // raise dynamic smem limit on the mma instantiations (via typed fn ptrs)
  {
    void (*k0)(const bf16*, const bf16*, const bf16*, const bf16*,
               float*, bf16*, bf16*, const float*,
               int, int, int, int, int,
               long long, long long, long long, long long, long long, long long, float);
    k0 = mma_gemm_kernel<false,false,0>;
    cudaFuncSetAttribute(k0, cudaFuncAttributeMaxDynamicSharedMemorySize, MMA_SMEM_BYTES);
    k0 = mma_gemm_kernel<false,false,1>;
    cudaFuncSetAttribute(k0, cudaFuncAttributeMaxDynamicSharedMemorySize, MMA_SMEM_BYTES);
    k0 = mma_gemm_kernel<false,false,2>;
    cudaFuncSetAttribute(k0, cudaFuncAttributeMaxDynamicSharedMemorySize, MMA_SMEM_BYTES);
    k0 = mma_gemm_kernel<true,true,2>;
    cudaFuncSetAttribute(k0, cudaFuncAttributeMaxDynamicSharedMemorySize, MMA_SMEM_BYTES);
    k0 = mma_gemm_kernel<false,true,1>;
    cudaFuncSetAttribute(k0, cudaFuncAttributeMaxDynamicSharedMemorySize, MMA_SMEM_BYTES);
  }

  float *p_xn, *p_src, *p_tmp, *p_vh, *p_logits;
  cudaGetSymbolAddress((void**)&p_xn, g_xn);
  cudaGetSymbolAddress((void**)&p_src, g_src);
  cudaGetSymbolAddress((void**)&p_tmp, g_tmp);
  cudaGetSymbolAddress((void**)&p_vh, g_vh);
  cudaGetSymbolAddress((void**)&p_logits, g_logits);
  bf16 *p_ah, *p_al, *p_qhh, *p_qhl, *p_khh, *p_khl;
  bf16 *p_vth, *p_vtl, *p_ph, *p_pl, *p_ffh, *p_ffl;
  cudaGetSymbolAddress((void**)&p_ah, g_ah);
  cudaGetSymbolAddress((void**)&p_al, g_al);
  cudaGetSymbolAddress((void**)&p_qhh, g_qhh);
  cudaGetSymbolAddress((void**)&p_qhl, g_qhl);
  cudaGetSymbolAddress((void**)&p_khh, g_khh);
  cudaGetSymbolAddress((void**)&p_khl, g_khl);
  cudaGetSymbolAddress((void**)&p_vth, g_vth);
  cudaGetSymbolAddress((void**)&p_vtl, g_vtl);
  cudaGetSymbolAddress((void**)&p_ph, g_ph);
  cudaGetSymbolAddress((void**)&p_pl, g_pl);
  cudaGetSymbolAddress((void**)&p_ffh, g_ffh);
  cudaGetSymbolAddress((void**)&p_ffl, g_ffl);
  bf16 *pWqh, *pWql, *pWkvh, *pWkvl, *pWoh, *pWol;
  bf16 *pW1h, *pW1l, *pW2h, *pW2l, *pHW1h, *pHW1l;
  cudaGetSymbolAddress((void**)&pWqh, g_WqTh);
  cudaGetSymbolAddress((void**)&pWql, g_WqTl);
  cudaGetSymbolAddress((void**)&pWkvh, g_WkvTh);
  cudaGetSymbolAddress((void**)&pWkvl, g_WkvTl);
  cudaGetSymbolAddress((void**)&pWoh, g_WoTh);
  cudaGetSymbolAddress((void**)&pWol, g_WoTl);
  cudaGetSymbolAddress((void**)&pW1h, g_W1Th);
  cudaGetSymbolAddress((void**)&pW1l, g_W1Tl);
  cudaGetSymbolAddress((void**)&pW2h, g_W2Th);
  cudaGetSymbolAddress((void**)&pW2l, g_W2Tl);
  cudaGetSymbolAddress((void**)&pHW1h, g_hW1Th);
  cudaGetSymbolAddress((void**)&pHW1l, g_hW1Tl);

  const float qk_scale = 0.08838834764831845f;

  // --- weight transpose+split ---
  transpose_split_kernel<<<dim3(DD/32, DD/32, NLAYERS), 256>>>(Wq, pWqh, pWql, DD, DD, (long long)DD*DD, (long long)DD*DD);
  transpose_split_kernel<<<dim3(2*DD/32, DD/32, NLAYERS), 256>>>(Wkv, pWkvh, pWkvl, DD, 2*DD, (long long)DD*2*DD, (long long)DD*2*DD);
  transpose_split_kernel<<<dim3(DD/32, DD/32, NLAYERS), 256>>>(Wout, pWoh, pWol, DD, DD, (long long)DD*DD, (long long)DD*DD);
  transpose_split_kernel<<<dim3(NHID/32, DD/32, NLAYERS), 256>>>(ffW1, pW1h, pW1l, DD, NHID, (long long)DD*NHID, (long long)DD*NHID);
  transpose_split_kernel<<<dim3(DD/32, NHID/32, NLAYERS), 256>>>(ffW2, pW2h, pW2l, NHID, DD, (long long)NHID*DD, (long long)NHID*DD);
  transpose_split_kernel<<<dim3(NHID/32, DD/32, 1), 256>>>(hW1, pHW1h, pHW1l, DD, NHID, 0, 0);

  // --- preprocessing + encoder (fp32 path) ---
  colstats_kernel<<<BB*NFEAT, 256>>>(x_src, 0);
  colstats_kernel<<<BB*NFEAT, 256>>>(x_src, 1);
  colstats_kernel<<<BB*NFEAT, 256>>>(x_src, 2);
  norm_write_kernel<<<(LB*KPAD + 255)/256, 256>>>(x_src);
  sgemm_kernel<true><<<dim3(DD/128, LB/128, 1), 256>>>(
      p_xn, enc_W, p_tmp, enc_b, KPAD, NFEAT, KPAD, DD, DD);
  encode_finish_kernel<<<LB, 256>>>(p_tmp, y_src, yenc_W, yenc_b);

  for (int i = 0; i < NLAYERS; i++) {
    // --- attention ---
    ln_split_kernel<<<LB, 256>>>(p_src, an_g + i*DD, an_b + i*DD, p_ah, p_al);
    // q = h @ Wq -> tmp (fp32)
    mma_gemm_kernel<false,false,0><<<dim3(8, 64, 1), 256, MMA_SMEM_BYTES>>>(
        p_ah, p_al, pWqh + (size_t)i*DD*DD, pWql + (size_t)i*DD*DD,
        p_tmp, nullptr, nullptr, nullptr,
        DD, DD, DD, DD, 1, 0,0,0,0,0,0, 1.f);
    qln_split_kernel<<<LB, 256>>>(p_tmp, qn_g + i*HDIM, qn_b + i*HDIM, p_qhh, p_qhl);
    // kv = h[:, :P] @ Wkv -> tmp (fp32), batched over b
    mma_gemm_kernel<false,false,0><<<dim3(16, 8, BB), 256, MMA_SMEM_BYTES>>>(
        p_ah, p_al, pWkvh + (size_t)i*DD*2*DD, pWkvl + (size_t)i*DD*2*DD,
        p_tmp, nullptr, nullptr, nullptr,
        DD, DD, DD, 2*DD, 1,
        (long long)LL*DD, 0, 0, 0, (long long)PP*2*DD, 0, 1.f);
    klnv_split_kernel<<<BB*PP, 256>>>(p_tmp, kn_g + i*HDIM, kn_b + i*HDIM, p_khh, p_khl, p_vh);
    // vT per (b,h): [P][HD] -> [HD][P]
    transpose_split_kernel<<<dim3(HDIM/32, PP/32, BB*HH), 256>>>(
        p_vh, p_vth, p_vtl, PP, HDIM, (long long)PP*HDIM, (long long)PP*HDIM);
    // logits = scale * q @ k^T, batched (b,h)
    mma_gemm_kernel<false,false,0><<<dim3(8, 16, BB*HH), 256, MMA_SMEM_BYTES>>>(
        p_qhh, p_qhl, p_khh, p_khl, p_logits, nullptr, nullptr, nullptr,
        HDIM, HDIM, HDIM, PP, 1,
        (long long)LL*HDIM, 0, (long long)PP*HDIM, 0, (long long)LL*PP, 0, qk_scale);
    softmax_split_kernel<<<BB*HH*LL, 256>>>(p_logits, p_ph, p_pl);
    // attn = probs @ vT^T -> split write into (B,L,H,HD) layout
    mma_gemm_kernel<false,false,2><<<dim3(1, 16, BB*HH), 256, MMA_SMEM_BYTES>>>(
        p_ph, p_pl, p_vth, p_vtl, nullptr, p_ah, p_al, nullptr,
        PP, PP, PP, DD, HH,
        (long long)HH*LL*PP, (long long)LL*PP,
        (long long)HH*HDIM*PP, (long long)HDIM*PP,
        (long long)LL*DD, (long long)HDIM, 1.f);
    // src += attn @ Wout
    mma_gemm_kernel<false,false,1><<<dim3(8, 64, 1), 256, MMA_SMEM_BYTES>>>(
        p_ah, p_al, pWoh + (size_t)i*DD*DD, pWol + (size_t)i*DD*DD,
        p_src, nullptr, nullptr, nullptr,
        DD, DD, DD, DD, 1, 0,0,0,0,0,0, 1.f);
    // --- FFN ---
    ln_split_kernel<<<LB, 256>>>(p_src, fn_g + i*DD, fn_b + i*DD, p_ah, p_al);
    mma_gemm_kernel<true,true,2><<<dim3(NHID/128, 64, 1), 256, MMA_SMEM_BYTES>>>(
        p_ah, p_al, pW1h + (size_t)i*NHID*DD, pW1l + (size_t)i*NHID*DD,
        nullptr, p_ffh, p_ffl, ffb1 + (size_t)i*NHID,
        DD, DD, DD, NHID, 1, 0,0,0,0,0,0, 1.f);
    mma_gemm_kernel<false,true,1><<<dim3(8, 64, 1), 256, MMA_SMEM_BYTES>>>(
        p_ffh, p_ffl, pW2h + (size_t)i*DD*NHID, pW2l + (size_t)i*DD*NHID,
        p_src, nullptr, nullptr, ffb2 + (size_t)i*DD,
        NHID, NHID, NHID, DD, 1, 0,0,0,0,0,0, 1.f);
  }

  // --- head ---
  split_rows_kernel<<<(LB*DD + 255)/256, 256>>>(p_src, p_ah, p_al, LB*DD);
  mma_gemm_kernel<true,true,2><<<dim3(NHID/128, PP/128, BB), 256, MMA_SMEM_BYTES>>>(
      p_ah + (size_t)PP*DD, p_al + (size_t)PP*DD, pHW1h, pHW1l,
      nullptr, p_ffh, p_ffl, hb1,
      DD, DD, DD, NHID, 1,
      (long long)LL*DD, 0, 0, 0, (long long)PP*NHID, 0, 1.f);
  head2_kernel<<<BB*PP, 256>>>(p_ffh, p_ffl, hW2, hb2, out);
}